// round 15
// baseline (speedup 1.0000x reference)
#include <cuda_runtime.h>
#include <cuda_bf16.h>
#include <cuda_fp16.h>
#include <cstdint>

// ---------------------------------------------------------------------------
// GAT layer: B=4, N=4096, F_in=F_out=128
// K1: Wh = h@W via m16n8k8 tf32 MMA -> g_Vt (fp16, transposed [b][f][j]),
//     si, sj (pre-scaled by log2 e)
// K2: WARP-SPECIALIZED fused masked-softmax + PV:
//     warps 0-3: produce fp16 P A-fragments (ballot masks + ex2) into PF[2]
//     warps 4-7: cp.async V staging + ldmatrix + m16n8k16 MMA (+ ones-MMA)
//     one named rendezvous barrier per tile (producer 1 tile ahead)
//     R13 bugfix: sj(jt+1) reload moved AFTER the P-compute phase.
// ---------------------------------------------------------------------------

#define NB   4
#define NN   4096
#define NF   128
#define BM   64
#define BN   64
#define NT   (NN / BN)

#define LOG2E 1.4426950408889634f
#define PSHIFT 10.0f

__device__ __half g_Vt[(size_t)NB * NF * NN];   // [b][f][j], fp16, 4 MB
__device__ float  g_si[NB * NN];     // scaled by LOG2E
__device__ float  g_sj[NB * NN];     // scaled by LOG2E

#define CP_ASYNC16(dst_u32, src_ptr) \
    asm volatile("cp.async.cg.shared.global [%0], [%1], 16;" \
                 :: "r"(dst_u32), "l"(src_ptr))
#define CP_COMMIT()  asm volatile("cp.async.commit_group;" ::: "memory")
#define CP_WAIT0()   asm volatile("cp.async.wait_group 0;"  ::: "memory")

#define BAR_SYNC(id, cnt) \
    asm volatile("bar.sync %0, %1;" :: "n"(id), "n"(cnt) : "memory")

__device__ __forceinline__ uint32_t tf32u(float x) {
    float y;
    asm("cvt.rna.tf32.f32 %0, %1;" : "=f"(y) : "f"(x));
    return __float_as_uint(y);
}

// ---------------------------------------------------------------------------
// Kernel 1: Wh = h @ W via tf32 MMA; outputs transposed fp16 V, si, sj.
// (unchanged from passing R12)
// ---------------------------------------------------------------------------
#define HS_S 132
#define WS_S 136
#define K1_SMEM_FLOATS (64 * HS_S + 128 * WS_S + 256)

__global__ __launch_bounds__(256, 2) void gat_k1(const float* __restrict__ h,
                                                 const float* __restrict__ W,
                                                 const float* __restrict__ a) {
    extern __shared__ float sm1[];
    float* hs  = sm1;                 // 64 x 132
    float* Ws  = sm1 + 64 * HS_S;     // 128 x 136
    float* red = Ws + 128 * WS_S;     // 64 x 2 x 2

    const int tid  = threadIdx.x;
    const int lane = tid & 31, warp = tid >> 5;
    const int gr   = blockIdx.x * 64;

    const uint32_t hs_b = (uint32_t)__cvta_generic_to_shared(hs);
    const uint32_t ws_b = (uint32_t)__cvta_generic_to_shared(Ws);
    {
        const float* hg = h + (size_t)gr * NF;
#pragma unroll
        for (int q = 0; q < 8; q++) {
            const int c = tid + q * 256;
            const int r = c >> 5, ch = c & 31;
            CP_ASYNC16(hs_b + (uint32_t)((r * HS_S + ch * 4) * 4),
                       hg + r * NF + ch * 4);
        }
#pragma unroll
        for (int q = 0; q < 16; q++) {
            const int c = tid + q * 256;
            const int r = c >> 5, ch = c & 31;
            CP_ASYNC16(ws_b + (uint32_t)((r * WS_S + ch * 4) * 4),
                       W + r * NF + ch * 4);
        }
    }
    CP_COMMIT(); CP_WAIT0();
    __syncthreads();

    const int wm  = (warp & 3) * 16;
    const int wnh = warp >> 2;
    const int ar  = lane >> 2, ac = lane & 3;

    float acc[8][4];
#pragma unroll
    for (int nt = 0; nt < 8; nt++)
#pragma unroll
        for (int e = 0; e < 4; e++) acc[nt][e] = 0.f;

#pragma unroll
    for (int kk = 0; kk < 16; kk++) {
        const int k0 = kk * 8;
        const uint32_t a0 = tf32u(hs[(wm + ar)     * HS_S + k0 + ac]);
        const uint32_t a1 = tf32u(hs[(wm + ar + 8) * HS_S + k0 + ac]);
        const uint32_t a2 = tf32u(hs[(wm + ar)     * HS_S + k0 + ac + 4]);
        const uint32_t a3 = tf32u(hs[(wm + ar + 8) * HS_S + k0 + ac + 4]);
#pragma unroll
        for (int nt = 0; nt < 8; nt++) {
            const int n0 = wnh * 64 + nt * 8;
            const uint32_t b0 = tf32u(Ws[(k0 + ac)     * WS_S + n0 + ar]);
            const uint32_t b1 = tf32u(Ws[(k0 + ac + 4) * WS_S + n0 + ar]);
            asm volatile(
                "mma.sync.aligned.m16n8k8.row.col.f32.tf32.tf32.f32 "
                "{%0,%1,%2,%3}, {%4,%5,%6,%7}, {%8,%9}, {%0,%1,%2,%3};\n"
                : "+f"(acc[nt][0]), "+f"(acc[nt][1]),
                  "+f"(acc[nt][2]), "+f"(acc[nt][3])
                : "r"(a0), "r"(a1), "r"(a2), "r"(a3), "r"(b0), "r"(b1));
        }
    }

    const int b   = gr >> 12;
    const int jin = gr & (NN - 1);
    const int r0  = wm + ar, r1 = wm + ar + 8;
    __half* vt = g_Vt + (size_t)b * NF * NN + jin;

    float pi0 = 0.f, pi1 = 0.f, pj0 = 0.f, pj1 = 0.f;
#pragma unroll
    for (int nt = 0; nt < 8; nt++) {
        const int c0 = wnh * 64 + nt * 8 + 2 * ac;
        const float ai0 = a[c0] * LOG2E,        ai1 = a[c0 + 1] * LOG2E;
        const float aj0 = a[NF + c0] * LOG2E,   aj1 = a[NF + c0 + 1] * LOG2E;
        vt[(size_t)c0 * NN + r0]       = __float2half_rn(acc[nt][0]);
        vt[(size_t)(c0 + 1) * NN + r0] = __float2half_rn(acc[nt][1]);
        vt[(size_t)c0 * NN + r1]       = __float2half_rn(acc[nt][2]);
        vt[(size_t)(c0 + 1) * NN + r1] = __float2half_rn(acc[nt][3]);
        pi0 += acc[nt][0] * ai0 + acc[nt][1] * ai1;
        pi1 += acc[nt][2] * ai0 + acc[nt][3] * ai1;
        pj0 += acc[nt][0] * aj0 + acc[nt][1] * aj1;
        pj1 += acc[nt][2] * aj0 + acc[nt][3] * aj1;
    }
#pragma unroll
    for (int off = 1; off <= 2; off <<= 1) {
        pi0 += __shfl_xor_sync(0xffffffffu, pi0, off);
        pi1 += __shfl_xor_sync(0xffffffffu, pi1, off);
        pj0 += __shfl_xor_sync(0xffffffffu, pj0, off);
        pj1 += __shfl_xor_sync(0xffffffffu, pj1, off);
    }
    if (ac == 0) {
        red[r0 * 4 + wnh * 2 + 0] = pi0;
        red[r0 * 4 + wnh * 2 + 1] = pj0;
        red[r1 * 4 + wnh * 2 + 0] = pi1;
        red[r1 * 4 + wnh * 2 + 1] = pj1;
    }
    __syncthreads();
    if (tid < 128) {
        const int row = tid >> 1, which = tid & 1;
        const float s = red[row * 4 + which] + red[row * 4 + 2 + which];
        (which ? g_sj : g_si)[gr + row] = s;
    }
}

// ---------------------------------------------------------------------------
// Kernel 2 — warp specialized
// smem: PF[2][2048 floats] fp16 A-frags, Vsw[2][128 x 36 words],
//       Msk[2][64][2] col-order ballot words
// ---------------------------------------------------------------------------
#define PF_FLOATS 2048
#define VT_WSTRIDE 36
#define VS_WORDS  (NF * VT_WSTRIDE)
#define SMEM_FLOATS (2 * PF_FLOATS + 2 * VS_WORDS + 4 * 64)

#define ONE2 0x3C003C00u

#define LDSM4(r0, r1, r2, r3, addr) \
    asm volatile("ldmatrix.sync.aligned.m8n8.x4.shared.b16 {%0,%1,%2,%3}, [%4];" \
                 : "=r"(r0), "=r"(r1), "=r"(r2), "=r"(r3) : "r"(addr))

__device__ __forceinline__ float pv(float si, float sj, uint32_t w, int bit) {
    float t = si + sj;
    float u = fminf(t, 0.f);
    float arg = fmaf(u, -0.8f, t) - PSHIFT;
    arg = ((w >> bit) & 1u) ? arg : -40.f;
    float e;
    asm("ex2.approx.f32 %0, %1;" : "=f"(e) : "f"(arg));
    return e;
}

#define MMA16(accv, af, b0, b1)                                            \
    asm volatile(                                                          \
        "mma.sync.aligned.m16n8k16.row.col.f32.f16.f16.f32 "               \
        "{%0,%1,%2,%3}, {%4,%5,%6,%7}, {%8,%9}, {%0,%1,%2,%3};\n"          \
        : "+f"(accv[0]), "+f"(accv[1]), "+f"(accv[2]), "+f"(accv[3])       \
        : "r"(af.x), "r"(af.y), "r"(af.z), "r"(af.w), "r"(b0), "r"(b1))

__global__ __launch_bounds__(256, 2) void gat_k2(const int* __restrict__ adj,
                                                 float* __restrict__ out) {
    extern __shared__ float smem[];
    float*     PF   = smem;                              // 2 x 2048 floats
    uint32_t*  Vsw  = (uint32_t*)(smem + 2 * PF_FLOATS); // 2 x 4608 words
    uint32_t*  Msk  = Vsw + 2 * VS_WORDS;                // 2 x 128 words

    const int tid  = threadIdx.x;
    const int lane = tid & 31, warp = tid >> 5;
    const int b  = blockIdx.x >> 6;
    const int i0 = (blockIdx.x & 63) * BM;

    const uint32_t vs_base = (uint32_t)__cvta_generic_to_shared(Vsw);

    if (warp < 4) {
        // ================= PRODUCERS (warps 0-3) =================
        const int kw   = warp;               // k16-chunk owned
        const int ar   = lane >> 2;
        const int ac   = lane & 3;
        const int c00  = 16 * kw + 2 * ac;
        const int bb   = 16 * (kw & 1) + 2 * ac;
        const int wsel = kw >> 1;
        const int grow = 16 * warp;          // 16 adj rows owned

        const int*   adj_b = adj + ((size_t)(b * NN + i0)) * NN;
        const float* sjb   = g_sj + b * NN;

        float sie[8];
#pragma unroll
        for (int ms = 0; ms < 4; ms++) {
            sie[2 * ms + 0] = g_si[b * NN + i0 + 16 * ms + ar];
            sie[2 * ms + 1] = g_si[b * NN + i0 + 16 * ms + ar + 8];
        }

        // prologue: adj(0), sj(0)
        int av[32];
#pragma unroll
        for (int i = 0; i < 16; i++) {
            const int* rowp = adj_b + (size_t)(grow + i) * NN;
            av[2 * i]     = rowp[lane];
            av[2 * i + 1] = rowp[lane + 32];
        }
        float2 sjA = *(const float2*)(sjb + c00);
        float2 sjB = *(const float2*)(sjb + c00 + 8);

        for (int jt = 0; jt < NT; jt++) {
            const int tb = jt & 1;

            // ---- ballots -> Msk[tb] (av holds adj of tile jt) ----
            uint32_t mw0 = 0, mw1 = 0;
#pragma unroll
            for (int i = 0; i < 16; i++) {
                const unsigned w0 = __ballot_sync(0xffffffffu, av[2 * i] != 0);
                const unsigned w1 = __ballot_sync(0xffffffffu, av[2 * i + 1] != 0);
                if (lane == i) { mw0 = w0; mw1 = w1; }
            }
            if (lane < 16) {
                uint2 m; m.x = mw0; m.y = mw1;
                *(uint2*)(Msk + tb * 128 + (grow + lane) * 2) = m;
            }
            BAR_SYNC(1, 128);   // producers: Msk[tb] complete (drains STS)

            // ---- prefetch adj(jt+1) only (av already consumed by ballots;
            //      sj must NOT be reloaded before the compute below!) ----
            if (jt + 1 < NT) {
                const int j1 = (jt + 1) * BN;
#pragma unroll
                for (int i = 0; i < 16; i++) {
                    const int* rowp = adj_b + (size_t)(grow + i) * NN + j1;
                    av[2 * i]     = rowp[lane];
                    av[2 * i + 1] = rowp[lane + 32];
                }
            }

            // ---- compute PF[tb] with CURRENT sjA/sjB ----
            const uint32_t* mk = Msk + tb * 128;
            uint4* pfb = (uint4*)(PF + tb * PF_FLOATS);
#pragma unroll
            for (int ms = 0; ms < 4; ms++) {
                const int r0 = 16 * ms + ar;
                const uint32_t w0 = mk[r0 * 2 + wsel];
                const uint32_t w1 = mk[(r0 + 8) * 2 + wsel];
                const float si0 = sie[2 * ms + 0];
                const float si1 = sie[2 * ms + 1];
                const float p00 = pv(si0, sjA.x, w0, bb);
                const float p01 = pv(si0, sjA.y, w0, bb + 1);
                const float p02 = pv(si0, sjB.x, w0, bb + 8);
                const float p03 = pv(si0, sjB.y, w0, bb + 9);
                const float p10 = pv(si1, sjA.x, w1, bb);
                const float p11 = pv(si1, sjA.y, w1, bb + 1);
                const float p12 = pv(si1, sjB.x, w1, bb + 8);
                const float p13 = pv(si1, sjB.y, w1, bb + 9);
                uint4 fr;
                __half2 t;
                t = __floats2half2_rn(p00, p01); fr.x = *(uint32_t*)&t;
                t = __floats2half2_rn(p10, p11); fr.y = *(uint32_t*)&t;
                t = __floats2half2_rn(p02, p03); fr.z = *(uint32_t*)&t;
                t = __floats2half2_rn(p12, p13); fr.w = *(uint32_t*)&t;
                pfb[(ms * 4 + kw) * 32 + lane] = fr;
            }

            // ---- NOW safe to load sj for jt+1 (consumed next iteration) ----
            if (jt + 1 < NT) {
                const int j1 = (jt + 1) * BN;
                sjA = *(const float2*)(sjb + j1 + c00);
                sjB = *(const float2*)(sjb + j1 + c00 + 8);
            }

            BAR_SYNC(3, 256);   // rendezvous: PF[tb] ready; consumer done (jt-1)
        }
    } else {
        // ================= CONSUMERS (warps 4-7) =================
        const int c    = warp - 4;
        const int ar   = lane >> 2;
        const int ac   = lane & 3;
        const int wm   = (c & 1) * 32;
        const int wn   = (c >> 1) * 64;
        const int ms0  = (c & 1) * 2;
        const int tid2 = tid - 128;          // 0..127

        const __half* Vtg = g_Vt + (size_t)b * NF * NN;

        // ldmatrix invariant offset
        const int mrow = lane & 7, mid = lane >> 3;
        const int ldBase = ((mid >> 1) * 8 + mrow) * VT_WSTRIDE + (mid & 1) * 4;

        float acc[2][8][4];
#pragma unroll
        for (int mt = 0; mt < 2; mt++)
#pragma unroll
            for (int nt = 0; nt < 8; nt++)
#pragma unroll
                for (int j = 0; j < 4; j++) acc[mt][nt][j] = 0.f;
        float acc_s[2][4];
#pragma unroll
        for (int mt = 0; mt < 2; mt++)
#pragma unroll
            for (int j = 0; j < 4; j++) acc_s[mt][j] = 0.f;

        // prologue: V(0) cp.async into buf0 (thread covers 2 rows x 4 chunks)
#pragma unroll
        for (int q = 0; q < 8; q++) {
            const int row = (tid2 >> 1) + (q >> 2) * 64;
            const int ch  = (tid2 & 1) * 4 + (q & 3);
            CP_ASYNC16(vs_base + (uint32_t)((row * VT_WSTRIDE + ch * 4) * 4),
                       Vtg + (size_t)row * NN + ch * 8);
        }
        CP_COMMIT();

        for (int jt = 0; jt < NT; jt++) {
            const int buf = jt & 1;

            CP_WAIT0();         // this thread's V(jt) copies landed
            BAR_SYNC(2, 128);   // all consumers' copies landed; MMA(jt-1) done
            BAR_SYNC(3, 256);   // rendezvous: PF[buf] ready

            // stage V(jt+1) into other buffer (safe: all consumers past bar2)
            if (jt + 1 < NT) {
                const int j1 = (jt + 1) * BN;
                const uint32_t vb = vs_base + (uint32_t)((buf ^ 1) * VS_WORDS * 4);
#pragma unroll
                for (int q = 0; q < 8; q++) {
                    const int row = (tid2 >> 1) + (q >> 2) * 64;
                    const int ch  = (tid2 & 1) * 4 + (q & 3);
                    CP_ASYNC16(vb + (uint32_t)((row * VT_WSTRIDE + ch * 4) * 4),
                               Vtg + (size_t)row * NN + j1 + ch * 8);
                }
                CP_COMMIT();
            }

            // ---- MMA: acc += P(64x64) @ V(64x128); acc_s += P @ ones ----
            const uint4*   pfr  = (const uint4*)(PF + buf * PF_FLOATS);
            const uint32_t vbuf = vs_base + (uint32_t)(buf * VS_WORDS * 4);
#pragma unroll
            for (int kk = 0; kk < 4; kk++) {
                const uint4 af0 = pfr[((ms0 + 0) * 4 + kk) * 32 + lane];
                const uint4 af1 = pfr[((ms0 + 1) * 4 + kk) * 32 + lane];
                MMA16(acc_s[0], af0, ONE2, ONE2);
                MMA16(acc_s[1], af1, ONE2, ONE2);
#pragma unroll
                for (int ntb = 0; ntb < 4; ntb++) {
                    uint32_t b0, b1, b2, b3;
                    LDSM4(b0, b1, b2, b3,
                          vbuf + (uint32_t)((((wn + ntb * 16) * VT_WSTRIDE) +
                                             ldBase + kk * 8) * 4));
                    MMA16(acc[0][2 * ntb],     af0, b0, b1);
                    MMA16(acc[1][2 * ntb],     af1, b0, b1);
                    MMA16(acc[0][2 * ntb + 1], af0, b2, b3);
                    MMA16(acc[1][2 * ntb + 1], af1, b2, b3);
                }
            }
        }

        // ---- epilogue: normalize, ELU, store ----
        const size_t obase = ((size_t)(b * NN + i0)) * NF;
#pragma unroll
        for (int mt = 0; mt < 2; mt++) {
            const int r0i = wm + mt * 16 + ar;
            const float rr0 = acc_s[mt][0];
            const float rr1 = acc_s[mt][2];
            const float inv0 = rr0 > 0.f ? 1.f / rr0 : 0.f;
            const float inv1 = rr1 > 0.f ? 1.f / rr1 : 0.f;
#pragma unroll
            for (int nt = 0; nt < 8; nt++) {
                const int col = wn + nt * 8 + ac * 2;
                float x0 = acc[mt][nt][0] * inv0, x1 = acc[mt][nt][1] * inv0;
                float y0 = acc[mt][nt][2] * inv1, y1 = acc[mt][nt][3] * inv1;
                x0 = x0 > 0.f ? x0 : expm1f(x0);
                x1 = x1 > 0.f ? x1 : expm1f(x1);
                y0 = y0 > 0.f ? y0 : expm1f(y0);
                y1 = y1 > 0.f ? y1 : expm1f(y1);
                *(float2*)(out + obase + (size_t)r0i * NF + col) =
                    make_float2(x0, x1);
                *(float2*)(out + obase + (size_t)(r0i + 8) * NF + col) =
                    make_float2(y0, y1);
            }
        }
    }
}

// ---------------------------------------------------------------------------
extern "C" void kernel_launch(void* const* d_in, const int* in_sizes, int n_in,
                              void* d_out, int out_size) {
    const float* h   = (const float*)d_in[0];
    const int*   adj = (const int*)d_in[1];
    const float* W   = (const float*)d_in[2];
    const float* a   = (const float*)d_in[3];
    float* out = (float*)d_out;

    static_assert(SMEM_FLOATS * 4 < 114 * 1024, "k2 smem too big for 2 CTAs/SM");
    static_assert(K1_SMEM_FLOATS * 4 < 114 * 1024, "k1 smem too big for 2 CTAs/SM");
    cudaFuncSetAttribute(gat_k1, cudaFuncAttributeMaxDynamicSharedMemorySize,
                         K1_SMEM_FLOATS * 4);
    cudaFuncSetAttribute(gat_k2, cudaFuncAttributeMaxDynamicSharedMemorySize,
                         SMEM_FLOATS * 4);

    gat_k1<<<(NB * NN) / 64, 256, K1_SMEM_FLOATS * 4>>>(h, W, a);
    gat_k2<<<NB * (NN / BM), 256, SMEM_FLOATS * 4>>>(adj, out);
}